// round 10
// baseline (speedup 1.0000x reference)
#include <cuda_runtime.h>
#include <cuda_bf16.h>
#include <cuda_fp16.h>
#include <math.h>
#include <stdint.h>

// Problem constants (fixed by the reference)
#define NN 50000
#define EE 1600000
#define FIN 256
#define OUTD 64
#define HEADS 8
#define HO 512   // HEADS*OUTD

// ---------------- device scratch (no allocs allowed) ----------------
__device__ __half g_T16[(size_t)NN * HO];  // transformed nodes + bias, fp16 [N, 512]
__device__ float g_Arx[NN * HEADS];        // exp(Ar + bias_r)  (exp hoisted out of agg)
__device__ int   g_cnt[NN];                // zero-init; cycle: count->0->cursor->0 (agg)
__device__ int   g_off[NN + 1];
__device__ int   g_col[EE];
__device__ int   g_part[128];

// ---------------- mma / ldmatrix helpers ----------------
__device__ __forceinline__ void mma_f16(float* d, const uint32_t* a, const uint32_t* b) {
  asm volatile(
      "mma.sync.aligned.m16n8k16.row.col.f32.f16.f16.f32 "
      "{%0,%1,%2,%3}, {%4,%5,%6,%7}, {%8,%9}, {%0,%1,%2,%3};"
      : "+f"(d[0]), "+f"(d[1]), "+f"(d[2]), "+f"(d[3])
      : "r"(a[0]), "r"(a[1]), "r"(a[2]), "r"(a[3]), "r"(b[0]), "r"(b[1]));
}

__device__ __forceinline__ void ldsm_x4(uint32_t* r, uint32_t saddr) {
  asm volatile(
      "ldmatrix.sync.aligned.m8n8.x4.shared.b16 {%0,%1,%2,%3}, [%4];"
      : "=r"(r[0]), "=r"(r[1]), "=r"(r[2]), "=r"(r[3])
      : "r"(saddr));
}

// ---------------- GEMM: T = X (M x 256) * W^T + bias -> fp16, fused exp(Ar) ----------------
// 256 threads, 8 warps (4m x 2n), warp tile 32x64 (one head wide). ldmatrix fragments.
// Prefetch pointers hoisted out of the k-loop (advance by +BK).
#define BM 128
#define BN 128
#define BK 32
#define HPITCH 40   // halves per smem row (80 B pitch; conflict-free for LDS & LDSM)

__global__ __launch_bounds__(256) void gemm_f16_kernel(
    const float* __restrict__ X, const float* __restrict__ W,
    const float* __restrict__ Wb, const float* __restrict__ As,
    const float* __restrict__ As_bias, int M) {
  __shared__ __half sA[BM][HPITCH];
  __shared__ __half sB[BN][HPITCH];
  const int bm = blockIdx.x * BM;
  const int bn = blockIdx.y * BN;
  const int tid = threadIdx.x;
  const int wid = tid >> 5, lane = tid & 31;
  const int wm = (wid & 3) * 32;   // warp m offset
  const int wn = (wid >> 2) * 64;  // warp n offset (one head)
  const int g = lane >> 2;
  const int t = lane & 3;

  const int lrow = lane & 15;
  const int lcol = (lane >> 4) * 8;
  const uint32_t sA_base = (uint32_t)__cvta_generic_to_shared(&sA[0][0]);
  const uint32_t sB_base = (uint32_t)__cvta_generic_to_shared(&sB[0][0]);
  const int aoff = (wm + lrow) * HPITCH + lcol;
  const int boff = (wn + lrow) * HPITCH + lcol;

  float acc[2][8][4];
#pragma unroll
  for (int mt = 0; mt < 2; mt++)
#pragma unroll
    for (int nt = 0; nt < 8; nt++)
#pragma unroll
      for (int j = 0; j < 4; j++) acc[mt][nt][j] = 0.f;

  // hoisted per-thread smem store indices and global base pointers
  int srow[4], sc4[4];
  const float* pA[4];
  const float* pB[4];
  bool vA[4];
#pragma unroll
  for (int i = 0; i < 4; i++) {
    int gi = tid + 256 * i;
    srow[i] = gi >> 3;
    sc4[i] = (gi & 7) * 4;
    vA[i] = (bm + srow[i]) < M;
    pA[i] = X + (size_t)(bm + srow[i]) * FIN + sc4[i];
    pB[i] = W + (size_t)(bn + srow[i]) * FIN + sc4[i];
  }

  float4 pa[4], pb[4];
#pragma unroll
  for (int i = 0; i < 4; i++) {
    pa[i] = vA[i] ? *(const float4*)pA[i] : make_float4(0.f, 0.f, 0.f, 0.f);
    pb[i] = *(const float4*)pB[i];
    pA[i] += BK;
    pB[i] += BK;
  }

  for (int k0 = 0; k0 < FIN; k0 += BK) {
#pragma unroll
    for (int i = 0; i < 4; i++) {
      __half2 a0 = __floats2half2_rn(pa[i].x, pa[i].y);
      __half2 a1 = __floats2half2_rn(pa[i].z, pa[i].w);
      *(uint2*)&sA[srow[i]][sc4[i]] = make_uint2(*(uint32_t*)&a0, *(uint32_t*)&a1);
      __half2 b0 = __floats2half2_rn(pb[i].x, pb[i].y);
      __half2 b1 = __floats2half2_rn(pb[i].z, pb[i].w);
      *(uint2*)&sB[srow[i]][sc4[i]] = make_uint2(*(uint32_t*)&b0, *(uint32_t*)&b1);
    }
    __syncthreads();

    if (k0 + BK < FIN) {
#pragma unroll
      for (int i = 0; i < 4; i++) {
        if (vA[i]) pa[i] = *(const float4*)pA[i];
        pb[i] = *(const float4*)pB[i];
        pA[i] += BK;
        pB[i] += BK;
      }
    }

#pragma unroll
    for (int k16 = 0; k16 < 2; k16++) {
      const int k = k16 * 16;
      uint32_t a[2][4], bb[4][4];
      ldsm_x4(a[0], sA_base + (uint32_t)(aoff + k) * 2);
      ldsm_x4(a[1], sA_base + (uint32_t)(aoff + 16 * HPITCH + k) * 2);
#pragma unroll
      for (int p = 0; p < 4; p++)
        ldsm_x4(bb[p], sB_base + (uint32_t)(boff + p * 16 * HPITCH + k) * 2);
#pragma unroll
      for (int mt = 0; mt < 2; mt++)
#pragma unroll
        for (int p = 0; p < 4; p++) {
          uint32_t b0[2] = {bb[p][0], bb[p][2]};
          uint32_t b1[2] = {bb[p][1], bb[p][3]};
          mma_f16(acc[mt][2 * p], a[mt], b0);
          mma_f16(acc[mt][2 * p + 1], a[mt], b1);
        }
    }
    __syncthreads();
  }

  // ---- epilogue: + Ws_bias (folded into T), store fp16, fused exp(Ar) ----
  const int head = (bn + wn) >> 6;
  float asr[16];
#pragma unroll
  for (int nt = 0; nt < 8; nt++) {
    int colh = nt * 8 + 2 * t;
    asr[nt * 2 + 0] = As[head * 128 + OUTD + colh];
    asr[nt * 2 + 1] = As[head * 128 + OUTD + colh + 1];
  }
  float arsum[4] = {0.f, 0.f, 0.f, 0.f};

#pragma unroll
  for (int mt = 0; mt < 2; mt++) {
    int r0 = bm + wm + mt * 16 + g;
#pragma unroll
    for (int nt = 0; nt < 8; nt++) {
      int c = bn + wn + nt * 8 + 2 * t;
      float wb0 = Wb[c], wb1 = Wb[c + 1];
      float v0 = acc[mt][nt][0] + wb0, v1 = acc[mt][nt][1] + wb1;
      float v2 = acc[mt][nt][2] + wb0, v3 = acc[mt][nt][3] + wb1;
      arsum[mt * 2 + 0] += v0 * asr[nt * 2] + v1 * asr[nt * 2 + 1];
      arsum[mt * 2 + 1] += v2 * asr[nt * 2] + v3 * asr[nt * 2 + 1];
      if (r0 < M)
        *(__half2*)&g_T16[(size_t)r0 * HO + c] = __floats2half2_rn(v0, v1);
      if (r0 + 8 < M)
        *(__half2*)&g_T16[(size_t)(r0 + 8) * HO + c] = __floats2half2_rn(v2, v3);
    }
  }
  float bias_r = As_bias[head * 2 + 1];
#pragma unroll
  for (int q = 0; q < 4; q++) {
    float v = arsum[q];
    v += __shfl_xor_sync(0xffffffffu, v, 1);
    v += __shfl_xor_sync(0xffffffffu, v, 2);
    if (t == 0) {
      int r = bm + wm + (q >> 1) * 16 + g + (q & 1) * 8;
      if (r < M) g_Arx[r * HEADS + head] = __expf(v + bias_r);  // exp hoisted here
    }
  }
}

// ---------------- CSR build ----------------
__global__ void count_kernel(const int* __restrict__ row, int E) {
  int e = blockIdx.x * blockDim.x + threadIdx.x;
  if (e < E) atomicAdd(&g_cnt[row[e]], 1);
}

__global__ __launch_bounds__(1024) void scan_blocks_kernel(int N) {
  __shared__ int warpsum[32];
  int tid = threadIdx.x, lane = tid & 31, w = tid >> 5;
  int i = blockIdx.x * 1024 + tid;
  int v = (i < N) ? g_cnt[i] : 0;
#pragma unroll
  for (int o = 1; o < 32; o <<= 1) {
    int u = __shfl_up_sync(0xffffffffu, v, o);
    if (lane >= o) v += u;
  }
  if (lane == 31) warpsum[w] = v;
  __syncthreads();
  if (w == 0) {
    int s = warpsum[lane];
#pragma unroll
    for (int o = 1; o < 32; o <<= 1) {
      int u = __shfl_up_sync(0xffffffffu, s, o);
      if (lane >= o) s += u;
    }
    warpsum[lane] = s;
    if (lane == 31) g_part[blockIdx.x] = s;
  }
  __syncthreads();
  int add = (w > 0) ? warpsum[w - 1] : 0;
  if (i < N) g_off[i + 1] = v + add;
}

__global__ void scan_part_kernel(int nb) {
  int lane = threadIdx.x;
  if (lane == 0) g_off[0] = 0;
  int carry = 0;
  for (int base = 0; base < nb; base += 32) {
    int v = (base + lane < nb) ? g_part[base + lane] : 0;
    int inc = v;
#pragma unroll
    for (int o = 1; o < 32; o <<= 1) {
      int u = __shfl_up_sync(0xffffffffu, inc, o);
      if (lane >= o) inc += u;
    }
    if (base + lane < nb) g_part[base + lane] = carry + inc - v;
    carry += __shfl_sync(0xffffffffu, inc, 31);
  }
}

__global__ void scan_add_kernel(int N) {
  int i = blockIdx.x * blockDim.x + threadIdx.x;
  if (i < N) {
    g_off[i + 1] += g_part[i >> 10];
    g_cnt[i] = 0;  // zero cursors for scatter
  }
}

__global__ void scatter_kernel(const int* __restrict__ row,
                               const int* __restrict__ col, int E) {
  int e = blockIdx.x * blockDim.x + threadIdx.x;
  if (e < E) {
    int r = row[e];
    int p = atomicAdd(&g_cnt[r], 1);
    g_col[g_off[r] + p] = col[e];
  }
}

// ---------------- aggregate: softmax over incoming edges + weighted gather ----------------
// One block/node, warp h = head h. exp precomputed in GEMM epilogue (g_Arx).
// Pass A: pure coalesced load + byte-offset precompute. Pass C: LDS.64 + LDG only.
#define SMAX 256
__global__ __launch_bounds__(256) void agg_kernel(
    const float* __restrict__ Wb, float* __restrict__ out, int N) {
  int n = blockIdx.x;
  int tid = threadIdx.x;
  int h = tid >> 5, l = tid & 31;
  int s = g_off[n];
  int deg = g_off[n + 1] - s;
  if (tid == 0) g_cnt[n] = 0;  // reset for next replay's count_kernel

  __shared__ float2 sfe[SMAX * 9];  // [i][h]: (exp(score), T-row byte offset)

  float2 acc = make_float2(0.f, 0.f);
  float inv = 0.f;

  if (deg > 0 && deg <= SMAX) {
    // pass A: coalesced exp load + byte offset (no MUFU here anymore)
    int tot = deg * 8;
    for (int idx = tid; idx < tot; idx += 256) {
      int i = idx >> 3, hh = idx & 7;
      int c = g_col[s + i];
      sfe[i * 9 + hh] = make_float2(g_Arx[c * HEADS + hh], __int_as_float(c * (HO * 2)));
    }
    __syncthreads();

    // pass B: per-head sum of unnormalized alpha
    float sum = 0.f;
    for (int i = l; i < deg; i += 32) sum += sfe[i * 9 + h].x;
#pragma unroll
    for (int o = 16; o; o >>= 1) sum += __shfl_xor_sync(0xffffffffu, sum, o);
    inv = 1.f / sum;

    // pass C: weighted fp16 gather; LDS.64 + IADD + LDG per edge
    const char* Tb = (const char*)g_T16 + (size_t)h * 128 + (size_t)l * 4;
#pragma unroll 8
    for (int i = 0; i < deg; i++) {
      float2 fc = sfe[i * 9 + h];
      __half2 tv = *(const __half2*)(Tb + __float_as_int(fc.y));
      float2 tf = __half22float2(tv);
      acc.x += fc.x * tf.x;
      acc.y += fc.x * tf.y;
    }
    acc.x *= inv;
    acc.y *= inv;
  } else if (deg > SMAX) {
    // fallback for huge degree: stream from global, exps precomputed
    float sum = 0.f;
    for (int i = l; i < deg; i += 32)
      sum += g_Arx[g_col[s + i] * HEADS + h];
#pragma unroll
    for (int o = 16; o; o >>= 1) sum += __shfl_xor_sync(0xffffffffu, sum, o);
    inv = 1.f / sum;
    const __half* Tb = g_T16 + (size_t)h * 64 + 2 * l;
    for (int i = 0; i < deg; i++) {
      int c = g_col[s + i];
      float a = g_Arx[c * HEADS + h];
      float2 tv = __half22float2(*(const __half2*)(Tb + (size_t)c * HO));
      acc.x += a * tv.x;
      acc.y += a * tv.y;
    }
    acc.x *= inv;
    acc.y *= inv;
  }

  // T rows carry Ws_bias and sum(alpha)=1 -> bias included when deg>0.
  int oc = h * 64 + 2 * l;
  float r0, r1;
  if (deg == 0) {
    r0 = Wb[oc];
    r1 = Wb[oc + 1];
  } else {
    r0 = acc.x;
    r1 = acc.y;
  }
  r0 = r0 > 0.f ? r0 : expm1f(r0);
  r1 = r1 > 0.f ? r1 : expm1f(r1);
  *(float2*)(out + (size_t)n * HO + oc) = make_float2(r0, r1);
}

// ---------------- launch ----------------
extern "C" void kernel_launch(void* const* d_in, const int* in_sizes, int n_in,
                              void* d_out, int out_size) {
  const float* x        = (const float*)d_in[0];
  const int*   edge_row = (const int*)d_in[1];
  const int*   edge_col = (const int*)d_in[2];
  const float* Ws       = (const float*)d_in[3];
  const float* Ws_bias  = (const float*)d_in[4];
  const float* As       = (const float*)d_in[5];
  const float* As_bias  = (const float*)d_in[6];
  float* out = (float*)d_out;

  const int N = in_sizes[0] / FIN;   // 50000
  const int E = in_sizes[1];         // 1600000

  // one-time stream/event setup (host objects only; no device memory)
  static cudaStream_t s2 = nullptr;
  static cudaEvent_t ev_fork = nullptr, ev_join = nullptr;
  if (s2 == nullptr) {
    cudaStreamCreateWithFlags(&s2, cudaStreamNonBlocking);
    cudaEventCreateWithFlags(&ev_fork, cudaEventDisableTiming);
    cudaEventCreateWithFlags(&ev_join, cudaEventDisableTiming);
  }

  int eb = (E + 255) / 256;
  int nb = (N + 1023) / 1024;

  // fork: CSR build on s2, concurrent with GEMM on the capture stream
  cudaEventRecord(ev_fork, 0);
  cudaStreamWaitEvent(s2, ev_fork, 0);
  count_kernel<<<eb, 256, 0, s2>>>(edge_row, E);
  scan_blocks_kernel<<<nb, 1024, 0, s2>>>(N);
  scan_part_kernel<<<1, 32, 0, s2>>>(nb);

  // main stream: GEMM (4th submission -> profiled by ncu)
  dim3 ggrid((N + BM - 1) / BM, HO / BN);
  gemm_f16_kernel<<<ggrid, 256>>>(x, Ws, Ws_bias, As, As_bias, N);

  scan_add_kernel<<<(N + 255) / 256, 256, 0, s2>>>(N);
  scatter_kernel<<<eb, 256, 0, s2>>>(edge_row, edge_col, E);
  cudaEventRecord(ev_join, s2);

  // join, then softmax + aggregate + ELU
  cudaStreamWaitEvent(0, ev_join, 0);
  agg_kernel<<<N, 256>>>(Ws_bias, out, N);
}

// round 11
// speedup vs baseline: 1.0705x; 1.0705x over previous
#include <cuda_runtime.h>
#include <cuda_bf16.h>
#include <cuda_fp16.h>
#include <math.h>
#include <stdint.h>

// Problem constants (fixed by the reference)
#define NN 50000
#define EE 1600000
#define FIN 256
#define OUTD 64
#define HEADS 8
#define HO 512   // HEADS*OUTD

// ---------------- device scratch (no allocs allowed) ----------------
__device__ __half g_T16[(size_t)NN * HO];  // transformed nodes + bias, fp16 [N, 512]
__device__ float g_Arx[NN * HEADS];        // exp(Ar + bias_r)
__device__ int   g_cnt[NN];                // zero-init; cycle: count->0->cursor->0 (agg)
__device__ int   g_off[NN + 1];
__device__ int   g_col[EE];
__device__ int   g_part[128];

// ---------------- mma / ldmatrix helpers ----------------
__device__ __forceinline__ void mma_f16(float* d, const uint32_t* a, const uint32_t* b) {
  asm volatile(
      "mma.sync.aligned.m16n8k16.row.col.f32.f16.f16.f32 "
      "{%0,%1,%2,%3}, {%4,%5,%6,%7}, {%8,%9}, {%0,%1,%2,%3};"
      : "+f"(d[0]), "+f"(d[1]), "+f"(d[2]), "+f"(d[3])
      : "r"(a[0]), "r"(a[1]), "r"(a[2]), "r"(a[3]), "r"(b[0]), "r"(b[1]));
}

__device__ __forceinline__ void ldsm_x4(uint32_t* r, uint32_t saddr) {
  asm volatile(
      "ldmatrix.sync.aligned.m8n8.x4.shared.b16 {%0,%1,%2,%3}, [%4];"
      : "=r"(r[0]), "=r"(r[1]), "=r"(r[2]), "=r"(r[3])
      : "r"(saddr));
}

// ---------------- GEMM: T = X (M x 256) * W^T + bias -> fp16, fused exp(Ar) ----------------
// 256 threads, 8 warps (4m x 2n), warp tile 32x64. No register prefetch; 2 CTAs/SM
// provide the load/MMA overlap instead (launch_bounds caps regs at 128).
#define BM 128
#define BN 128
#define BK 32
#define HPITCH 40   // halves per smem row (80 B pitch; conflict-free for LDS & LDSM)

__global__ __launch_bounds__(256, 2) void gemm_f16_kernel(
    const float* __restrict__ X, const float* __restrict__ W,
    const float* __restrict__ Wb, const float* __restrict__ As,
    const float* __restrict__ As_bias, int M) {
  __shared__ __half sA[BM][HPITCH];
  __shared__ __half sB[BN][HPITCH];
  const int bm = blockIdx.x * BM;
  const int bn = blockIdx.y * BN;
  const int tid = threadIdx.x;
  const int wid = tid >> 5, lane = tid & 31;
  const int wm = (wid & 3) * 32;   // warp m offset
  const int wn = (wid >> 2) * 64;  // warp n offset (one head)
  const int g = lane >> 2;
  const int t = lane & 3;

  const int lrow = lane & 15;
  const int lcol = (lane >> 4) * 8;
  const uint32_t sA_base = (uint32_t)__cvta_generic_to_shared(&sA[0][0]);
  const uint32_t sB_base = (uint32_t)__cvta_generic_to_shared(&sB[0][0]);
  const int aoff = (wm + lrow) * HPITCH + lcol;
  const int boff = (wn + lrow) * HPITCH + lcol;

  float acc[2][8][4];
#pragma unroll
  for (int mt = 0; mt < 2; mt++)
#pragma unroll
    for (int nt = 0; nt < 8; nt++)
#pragma unroll
      for (int j = 0; j < 4; j++) acc[mt][nt][j] = 0.f;

  // per-thread load slots (4 float4 per matrix per tile)
  int srow[4], sc4[4];
  const float* pA[4];
  const float* pB[4];
  bool vA[4];
#pragma unroll
  for (int i = 0; i < 4; i++) {
    int gi = tid + 256 * i;
    srow[i] = gi >> 3;
    sc4[i] = (gi & 7) * 4;
    vA[i] = (bm + srow[i]) < M;
    pA[i] = X + (size_t)(bm + srow[i]) * FIN + sc4[i];
    pB[i] = W + (size_t)(bn + srow[i]) * FIN + sc4[i];
  }

  for (int k0 = 0; k0 < FIN; k0 += BK) {
    // ---- load + convert + store to smem (no staging across iterations) ----
#pragma unroll
    for (int i = 0; i < 4; i++) {
      float4 va = vA[i] ? *(const float4*)pA[i] : make_float4(0.f, 0.f, 0.f, 0.f);
      float4 vb = *(const float4*)pB[i];
      pA[i] += BK;
      pB[i] += BK;
      __half2 a0 = __floats2half2_rn(va.x, va.y);
      __half2 a1 = __floats2half2_rn(va.z, va.w);
      *(uint2*)&sA[srow[i]][sc4[i]] = make_uint2(*(uint32_t*)&a0, *(uint32_t*)&a1);
      __half2 b0 = __floats2half2_rn(vb.x, vb.y);
      __half2 b1 = __floats2half2_rn(vb.z, vb.w);
      *(uint2*)&sB[srow[i]][sc4[i]] = make_uint2(*(uint32_t*)&b0, *(uint32_t*)&b1);
    }
    __syncthreads();

#pragma unroll
    for (int k16 = 0; k16 < 2; k16++) {
      const int k = k16 * 16;
      uint32_t a[2][4], bb[4][4];
      ldsm_x4(a[0], sA_base + (uint32_t)(aoff + k) * 2);
      ldsm_x4(a[1], sA_base + (uint32_t)(aoff + 16 * HPITCH + k) * 2);
#pragma unroll
      for (int p = 0; p < 4; p++)
        ldsm_x4(bb[p], sB_base + (uint32_t)(boff + p * 16 * HPITCH + k) * 2);
#pragma unroll
      for (int mt = 0; mt < 2; mt++)
#pragma unroll
        for (int p = 0; p < 4; p++) {
          uint32_t b0[2] = {bb[p][0], bb[p][2]};
          uint32_t b1[2] = {bb[p][1], bb[p][3]};
          mma_f16(acc[mt][2 * p], a[mt], b0);
          mma_f16(acc[mt][2 * p + 1], a[mt], b1);
        }
    }
    __syncthreads();
  }

  // ---- epilogue: + Ws_bias (folded into T), store fp16, fused exp(Ar) ----
  const int head = (bn + wn) >> 6;
  float asr[16];
#pragma unroll
  for (int nt = 0; nt < 8; nt++) {
    int colh = nt * 8 + 2 * t;
    asr[nt * 2 + 0] = As[head * 128 + OUTD + colh];
    asr[nt * 2 + 1] = As[head * 128 + OUTD + colh + 1];
  }
  float arsum[4] = {0.f, 0.f, 0.f, 0.f};

#pragma unroll
  for (int mt = 0; mt < 2; mt++) {
    int r0 = bm + wm + mt * 16 + g;
#pragma unroll
    for (int nt = 0; nt < 8; nt++) {
      int c = bn + wn + nt * 8 + 2 * t;
      float wb0 = Wb[c], wb1 = Wb[c + 1];
      float v0 = acc[mt][nt][0] + wb0, v1 = acc[mt][nt][1] + wb1;
      float v2 = acc[mt][nt][2] + wb0, v3 = acc[mt][nt][3] + wb1;
      arsum[mt * 2 + 0] += v0 * asr[nt * 2] + v1 * asr[nt * 2 + 1];
      arsum[mt * 2 + 1] += v2 * asr[nt * 2] + v3 * asr[nt * 2 + 1];
      if (r0 < M)
        *(__half2*)&g_T16[(size_t)r0 * HO + c] = __floats2half2_rn(v0, v1);
      if (r0 + 8 < M)
        *(__half2*)&g_T16[(size_t)(r0 + 8) * HO + c] = __floats2half2_rn(v2, v3);
    }
  }
  float bias_r = As_bias[head * 2 + 1];
#pragma unroll
  for (int q = 0; q < 4; q++) {
    float v = arsum[q];
    v += __shfl_xor_sync(0xffffffffu, v, 1);
    v += __shfl_xor_sync(0xffffffffu, v, 2);
    if (t == 0) {
      int r = bm + wm + (q >> 1) * 16 + g + (q & 1) * 8;
      if (r < M) g_Arx[r * HEADS + head] = __expf(v + bias_r);
    }
  }
}

// ---------------- CSR build ----------------
__global__ void count_kernel(const int* __restrict__ row, int E) {
  int e = blockIdx.x * blockDim.x + threadIdx.x;
  if (e < E) atomicAdd(&g_cnt[row[e]], 1);
}

__global__ __launch_bounds__(1024) void scan_blocks_kernel(int N) {
  __shared__ int warpsum[32];
  int tid = threadIdx.x, lane = tid & 31, w = tid >> 5;
  int i = blockIdx.x * 1024 + tid;
  int v = (i < N) ? g_cnt[i] : 0;
#pragma unroll
  for (int o = 1; o < 32; o <<= 1) {
    int u = __shfl_up_sync(0xffffffffu, v, o);
    if (lane >= o) v += u;
  }
  if (lane == 31) warpsum[w] = v;
  __syncthreads();
  if (w == 0) {
    int s = warpsum[lane];
#pragma unroll
    for (int o = 1; o < 32; o <<= 1) {
      int u = __shfl_up_sync(0xffffffffu, s, o);
      if (lane >= o) s += u;
    }
    warpsum[lane] = s;
    if (lane == 31) g_part[blockIdx.x] = s;
  }
  __syncthreads();
  int add = (w > 0) ? warpsum[w - 1] : 0;
  if (i < N) g_off[i + 1] = v + add;
}

__global__ void scan_part_kernel(int nb) {
  int lane = threadIdx.x;
  if (lane == 0) g_off[0] = 0;
  int carry = 0;
  for (int base = 0; base < nb; base += 32) {
    int v = (base + lane < nb) ? g_part[base + lane] : 0;
    int inc = v;
#pragma unroll
    for (int o = 1; o < 32; o <<= 1) {
      int u = __shfl_up_sync(0xffffffffu, inc, o);
      if (lane >= o) inc += u;
    }
    if (base + lane < nb) g_part[base + lane] = carry + inc - v;
    carry += __shfl_sync(0xffffffffu, inc, 31);
  }
}

__global__ void scan_add_kernel(int N) {
  int i = blockIdx.x * blockDim.x + threadIdx.x;
  if (i < N) {
    g_off[i + 1] += g_part[i >> 10];
    g_cnt[i] = 0;  // zero cursors for scatter
  }
}

__global__ void scatter_kernel(const int* __restrict__ row,
                               const int* __restrict__ col, int E) {
  int e = blockIdx.x * blockDim.x + threadIdx.x;
  if (e < E) {
    int r = row[e];
    int p = atomicAdd(&g_cnt[r], 1);
    g_col[g_off[r] + p] = col[e];
  }
}

// ---------------- aggregate: softmax over incoming edges + weighted gather ----------------
// One block/node, warp h = head h. exp precomputed (g_Arx). Pass C: 2 edges per
// warp iteration — lanes 0-15 edge i, lanes 16-31 edge i+1, uint2 per lane;
// one LDS.64 + one LDG.64 per 2 edges. Odd edge handled in epilogue.
#define SMAX 256
__global__ __launch_bounds__(256) void agg_kernel(
    const float* __restrict__ Wb, float* __restrict__ out, int N) {
  int n = blockIdx.x;
  int tid = threadIdx.x;
  int h = tid >> 5, l = tid & 31;
  int half = l >> 4, sl = l & 15;
  int s = g_off[n];
  int deg = g_off[n + 1] - s;
  if (tid == 0) g_cnt[n] = 0;  // reset for next replay's count_kernel

  __shared__ float2 sfe[SMAX * 9];  // [i][h]: (exp(score), T-row byte offset)

  float acc4[4] = {0.f, 0.f, 0.f, 0.f};
  float inv = 0.f;

  if (deg > 0 && deg <= SMAX) {
    // pass A: coalesced exp load + byte offset
    int tot = deg * 8;
    for (int idx = tid; idx < tot; idx += 256) {
      int i = idx >> 3, hh = idx & 7;
      int c = g_col[s + i];
      sfe[i * 9 + hh] = make_float2(g_Arx[c * HEADS + hh], __int_as_float(c * (HO * 2)));
    }
    __syncthreads();

    // pass B: per-head sum of unnormalized alpha
    float sum = 0.f;
    for (int i = l; i < deg; i += 32) sum += sfe[i * 9 + h].x;
#pragma unroll
    for (int o = 16; o; o >>= 1) sum += __shfl_xor_sync(0xffffffffu, sum, o);
    inv = 1.f / sum;

    // pass C: 2 edges per iteration; lane covers 4 cols (8 B) of its edge's slice
    const char* Tb = (const char*)g_T16 + (size_t)h * 128 + (size_t)sl * 8;
    int deg2 = deg & ~1;
#pragma unroll 4
    for (int i = 0; i < deg2; i += 2) {
      float2 fc = sfe[(i + half) * 9 + h];
      uint2 raw = *(const uint2*)(Tb + __float_as_int(fc.y));
      float2 f0 = __half22float2(*(__half2*)&raw.x);
      float2 f1 = __half22float2(*(__half2*)&raw.y);
      acc4[0] += fc.x * f0.x;
      acc4[1] += fc.x * f0.y;
      acc4[2] += fc.x * f1.x;
      acc4[3] += fc.x * f1.y;
    }
    if (deg & 1) {
      float2 fc = sfe[deg2 * 9 + h];
      if (half == 0) {
        uint2 raw = *(const uint2*)(Tb + __float_as_int(fc.y));
        float2 f0 = __half22float2(*(__half2*)&raw.x);
        float2 f1 = __half22float2(*(__half2*)&raw.y);
        acc4[0] += fc.x * f0.x;
        acc4[1] += fc.x * f0.y;
        acc4[2] += fc.x * f1.x;
        acc4[3] += fc.x * f1.y;
      }
    }
  } else if (deg > SMAX) {
    // fallback for huge degree: stream from global, exps precomputed
    float sum = 0.f;
    for (int i = l; i < deg; i += 32)
      sum += g_Arx[g_col[s + i] * HEADS + h];
#pragma unroll
    for (int o = 16; o; o >>= 1) sum += __shfl_xor_sync(0xffffffffu, sum, o);
    inv = 1.f / sum;
    const char* Tb = (const char*)g_T16 + (size_t)h * 128 + (size_t)sl * 8;
    int deg2 = deg & ~1;
    for (int i = 0; i < deg2; i += 2) {
      int c = g_col[s + i + half];
      float a = g_Arx[c * HEADS + h];
      uint2 raw = *(const uint2*)(Tb + (size_t)c * (HO * 2));
      float2 f0 = __half22float2(*(__half2*)&raw.x);
      float2 f1 = __half22float2(*(__half2*)&raw.y);
      acc4[0] += a * f0.x;
      acc4[1] += a * f0.y;
      acc4[2] += a * f1.x;
      acc4[3] += a * f1.y;
    }
    if (deg & 1) {
      int c = g_col[s + deg2];
      float a = g_Arx[c * HEADS + h];
      if (half == 0) {
        uint2 raw = *(const uint2*)(Tb + (size_t)c * (HO * 2));
        float2 f0 = __half22float2(*(__half2*)&raw.x);
        float2 f1 = __half22float2(*(__half2*)&raw.y);
        acc4[0] += a * f0.x;
        acc4[1] += a * f0.y;
        acc4[2] += a * f1.x;
        acc4[3] += a * f1.y;
      }
    }
  }

  // combine the two lane-halves; lanes 0-15 of each warp store 4 cols
#pragma unroll
  for (int j = 0; j < 4; j++) acc4[j] += __shfl_xor_sync(0xffffffffu, acc4[j], 16);
  if (half == 0) {
    int oc = h * 64 + 4 * sl;
    float4 r;
    if (deg == 0) {  // T carries Ws_bias and sum(alpha)=1 otherwise
      r.x = Wb[oc]; r.y = Wb[oc + 1]; r.z = Wb[oc + 2]; r.w = Wb[oc + 3];
    } else {
      r.x = acc4[0] * inv; r.y = acc4[1] * inv; r.z = acc4[2] * inv; r.w = acc4[3] * inv;
    }
    r.x = r.x > 0.f ? r.x : expm1f(r.x);
    r.y = r.y > 0.f ? r.y : expm1f(r.y);
    r.z = r.z > 0.f ? r.z : expm1f(r.z);
    r.w = r.w > 0.f ? r.w : expm1f(r.w);
    *(float4*)(out + (size_t)n * HO + oc) = r;
  }
}

// ---------------- launch ----------------
extern "C" void kernel_launch(void* const* d_in, const int* in_sizes, int n_in,
                              void* d_out, int out_size) {
  const float* x        = (const float*)d_in[0];
  const int*   edge_row = (const int*)d_in[1];
  const int*   edge_col = (const int*)d_in[2];
  const float* Ws       = (const float*)d_in[3];
  const float* Ws_bias  = (const float*)d_in[4];
  const float* As       = (const float*)d_in[5];
  const float* As_bias  = (const float*)d_in[6];
  float* out = (float*)d_out;

  const int N = in_sizes[0] / FIN;   // 50000
  const int E = in_sizes[1];         // 1600000

  // one-time stream/event setup (host objects only; no device memory)
  static cudaStream_t s2 = nullptr;
  static cudaEvent_t ev_fork = nullptr, ev_join = nullptr;
  if (s2 == nullptr) {
    cudaStreamCreateWithFlags(&s2, cudaStreamNonBlocking);
    cudaEventCreateWithFlags(&ev_fork, cudaEventDisableTiming);
    cudaEventCreateWithFlags(&ev_join, cudaEventDisableTiming);
  }

  int eb = (E + 255) / 256;
  int nb = (N + 1023) / 1024;

  // fork: CSR build on s2, concurrent with GEMM on the capture stream
  cudaEventRecord(ev_fork, 0);
  cudaStreamWaitEvent(s2, ev_fork, 0);
  count_kernel<<<eb, 256, 0, s2>>>(edge_row, E);
  scan_blocks_kernel<<<nb, 1024, 0, s2>>>(N);
  scan_part_kernel<<<1, 32, 0, s2>>>(nb);

  // main stream: GEMM (4th submission -> profiled by ncu)
  dim3 ggrid((N + BM - 1) / BM, HO / BN);
  gemm_f16_kernel<<<ggrid, 256>>>(x, Ws, Ws_bias, As, As_bias, N);

  scan_add_kernel<<<(N + 255) / 256, 256, 0, s2>>>(N);
  scatter_kernel<<<eb, 256, 0, s2>>>(edge_row, edge_col, E);
  cudaEventRecord(ev_join, s2);

  // join, then softmax + aggregate + ELU
  cudaStreamWaitEvent(0, ev_join, 0);
  agg_kernel<<<N, 256>>>(Ws_bias, out, N);
}